// round 1
// baseline (speedup 1.0000x reference)
#include <cuda_runtime.h>

#define MM 512
#define NN 512
#define NPIX (MM*NN)

// Scratch (device globals — no allocation allowed)
__device__ float2 g_tmp[NPIX];    // horizontal box sums {sx, sy}
__device__ float2 g_base[NPIX];   // {Xb, yb}
__device__ float2 g_det[NPIX];    // {Xd, yd - Xd}
__device__ unsigned g_minbits, g_maxbits;
__device__ float g_C;             // -1/(sigma/2)^2

__device__ __forceinline__ unsigned f2key(float f) {
    unsigned u = __float_as_uint(f);
    return (u & 0x80000000u) ? ~u : (u | 0x80000000u);
}
__device__ __forceinline__ float key2f(unsigned k) {
    unsigned u = (k & 0x80000000u) ? (k ^ 0x80000000u) : ~k;
    return __uint_as_float(u);
}

__global__ void k_init() {
    g_minbits = 0xFFFFFFFFu;
    g_maxbits = 0u;
}

__global__ void k_minmax(const float* __restrict__ y) {
    unsigned tid = blockIdx.x * blockDim.x + threadIdx.x;
    unsigned stride = gridDim.x * blockDim.x;
    unsigned mn = 0xFFFFFFFFu, mx = 0u;
    for (unsigned i = tid; i < (unsigned)NPIX; i += stride) {
        unsigned k = f2key(y[i]);
        mn = min(mn, k);
        mx = max(mx, k);
    }
    #pragma unroll
    for (int o = 16; o; o >>= 1) {
        mn = min(mn, __shfl_xor_sync(0xFFFFFFFFu, mn, o));
        mx = max(mx, __shfl_xor_sync(0xFFFFFFFFu, mx, o));
    }
    if ((threadIdx.x & 31u) == 0u) {
        atomicMin(&g_minbits, mn);
        atomicMax(&g_maxbits, mx);
    }
}

__global__ void k_final(const float* __restrict__ r) {
    float mx = key2f(g_maxbits), mn = key2f(g_minbits);
    float sigma = r[0] * (mx - mn);
    float h = sigma * 0.5f;
    g_C = -1.0f / (h * h);
}

// Horizontal 9-tap sum (zero padding)
__global__ void k_hbox(const float* __restrict__ X, const float* __restrict__ Y) {
    int idx = blockIdx.x * 256 + threadIdx.x;
    int i = idx >> 9, j = idx & 511;
    float sx = 0.f, sy = 0.f;
    #pragma unroll
    for (int d = -4; d <= 4; ++d) {
        int jj = j + d;
        if ((unsigned)jj < 512u) {
            sx += X[(i << 9) + jj];
            sy += Y[(i << 9) + jj];
        }
    }
    g_tmp[idx] = make_float2(sx, sy);
}

// Vertical 9-tap sum, /81, then derive detail images
__global__ void k_vbox(const float* __restrict__ X, const float* __restrict__ Y) {
    int idx = blockIdx.x * 256 + threadIdx.x;
    int i = idx >> 9, j = idx & 511;
    float sx = 0.f, sy = 0.f;
    #pragma unroll
    for (int d = -4; d <= 4; ++d) {
        int ii = i + d;
        if ((unsigned)ii < 512u) {
            float2 t = g_tmp[(ii << 9) + j];
            sx += t.x;
            sy += t.y;
        }
    }
    const float inv81 = 1.0f / 81.0f;
    float xb = sx * inv81, yb = sy * inv81;
    float x = X[idx], y = Y[idx];
    float xd = x - xb;
    float zd = (y - yb) - xd;
    g_base[idx] = make_float2(xb, yb);
    g_det[idx]  = make_float2(xd, zd);
}

#define BX 32
#define BY 8
#define HB 9
#define TW (BX + 2 * HB)   // 50
#define TH (BY + 2 * HB)   // 26
#define HDR 2
#define HDC 4
#define DW (BX + 2 * HDC)  // 40
#define DH (BY + 2 * HDR)  // 12

__global__ __launch_bounds__(256) void k_main(float* __restrict__ out) {
    __shared__ float2 sb[TH][TW];
    __shared__ float2 sd[DH][DW];

    int tx = threadIdx.x, ty = threadIdx.y;
    int bx = blockIdx.x * BX, by = blockIdx.y * BY;
    int tid = ty * BX + tx;

    // Fill base tile (clamped loads; validity enforced by masks later)
    for (int k = tid; k < TH * TW; k += 256) {
        int r = k / TW, c = k % TW;
        int gi = min(max(by + r - HB, 0), 511);
        int gj = min(max(bx + c - HB, 0), 511);
        sb[r][c] = g_base[(gi << 9) + gj];
    }
    for (int k = tid; k < DH * DW; k += 256) {
        int r = k / DW, c = k % DW;
        int gi = min(max(by + r - HDR, 0), 511);
        int gj = min(max(bx + c - HDC, 0), 511);
        sd[r][c] = g_det[(gi << 9) + gj];
    }
    __syncthreads();

    int gi = by + ty, gj = bx + tx;

    // Chunk assignment: output col j -> chunk k, valid cols [cs, ce)
    int kch = (gj - 1) / 62;           // gj=0 -> -1/62 == 0 (trunc)
    kch = min(kch, 8);
    int cs = 62 * kch;
    int ce = min(cs + 64, 512);

    float C = g_C;

    // ---------------- Base: 19x19 bilateral moments on Xb ----------------
    float2 cb = sb[ty + HB][tx + HB];
    float xc = cb.x;

    unsigned cm;
    {
        int lo = max(cs - (gj - HB), 0);
        int hi = min(ce - (gj - HB), 19);
        cm = (hi > lo) ? (((1u << hi) - 1u) & ~((1u << lo) - 1u)) : 0u;
    }

    float sw = 0.f, swx = 0.f, swxx = 0.f, swy = 0.f, swxy = 0.f;
    const float invS1 = 1.0f / 8145.0625f;   // (19*19/4)^2

    for (int di = 0; di < 19; ++di) {
        bool rok = (unsigned)(gi + di - HB) < 512u;
        unsigned m = rok ? cm : 0u;
        int dd = di - HB;
        float lr = -(float)(dd * dd) * invS1;
        const float2* row = &sb[ty + di][tx];
        #pragma unroll
        for (int dj = 0; dj < 19; ++dj) {
            float2 v = row[dj];
            int cc = dj - HB;
            float L = lr - (float)(cc * cc) * invS1;   // constant-folded per dj
            float d = v.x - xc;
            float arg = fmaf(d * C, d, L);
            float w = __expf(arg);
            w = ((m >> dj) & 1u) ? w : 0.0f;
            sw += w;
            float wx = w * v.x;
            swx += wx;
            swxx = fmaf(wx, v.x, swxx);
            swy  = fmaf(w,  v.y, swy);
            swxy = fmaf(wx, v.y, swxy);
        }
    }

    // ---------------- Detail: 5x9 bilateral on Xd ----------------
    float2 cd = sd[ty + HDR][tx + HDC];
    float xdc = cd.x;

    unsigned cmd;
    {
        int lo = max(cs - (gj - HDC), 0);
        int hi = min(ce - (gj - HDC), 9);
        cmd = (hi > lo) ? (((1u << hi) - 1u) & ~((1u << lo) - 1u)) : 0u;
    }

    float swd = 0.f, swdz = 0.f;
    const float invS0 = 1.0f / 126.5625f;    // (5*9/4)^2
    #pragma unroll
    for (int di = 0; di < 5; ++di) {
        bool rok = (unsigned)(gi + di - HDR) < 512u;
        unsigned m = rok ? cmd : 0u;
        int dd = di - HDR;
        float lr = -(float)(dd * dd) * invS0;
        const float2* row = &sd[ty + di][tx];
        #pragma unroll
        for (int dj = 0; dj < 9; ++dj) {
            float2 v = row[dj];
            int cc = dj - HDC;
            float L = lr - (float)(cc * cc) * invS0;
            float d = v.x - xdc;
            float arg = fmaf(d * C, d, L);
            float w = __expf(arg);
            w = ((m >> dj) & 1u) ? w : 0.0f;
            swd += w;
            swdz = fmaf(w, v.y, swdz);
        }
    }

    // ---------------- Combine ----------------
    float invsw = 1.0f / sw;
    float mx = swx * invsw, my = swy * invsw;
    float var = fmaf(-mx, mx, swxx * invsw);
    float cov = fmaf(-mx, my, swxy * invsw);
    float A = cov / (var + 1e-6f);
    float b = fmaf(-A, mx, my);
    float bdet = swdz / swd;

    out[(gi << 9) + gj] = fmaf(A, xc, b + cd.x + bdet);
}

extern "C" void kernel_launch(void* const* d_in, const int* in_sizes, int n_in,
                              void* d_out, int out_size) {
    const float* X = (const float*)d_in[0];
    const float* Y = (const float*)d_in[1];
    const float* R = (const float*)d_in[2];
    float* out = (float*)d_out;

    k_init<<<1, 1>>>();
    k_minmax<<<256, 256>>>(Y);
    k_final<<<1, 1>>>(R);
    k_hbox<<<NPIX / 256, 256>>>(X, Y);
    k_vbox<<<NPIX / 256, 256>>>(X, Y);
    k_main<<<dim3(NN / BX, MM / BY), dim3(BX, BY)>>>(out);
}

// round 2
// speedup vs baseline: 1.0868x; 1.0868x over previous
#include <cuda_runtime.h>

#define MM 512
#define NN 512
#define NPIX (MM*NN)

typedef unsigned long long u64;

__device__ float2 g_base[NPIX];   // {Xb, yb}
__device__ float2 g_det[NPIX];    // {Xd, yd - Xd}
__device__ unsigned g_minbits, g_maxbits;
__device__ float g_C;             // -log2e/(sigma/2)^2  (pre-scaled for ex2)

#define LOG2E 1.4426950408889634f

// ---- packed f32x2 helpers ----
#define FMA2(d,a,b,c) asm("fma.rn.f32x2 %0, %1, %2, %3;" : "=l"(d) : "l"(a), "l"(b), "l"(c))
#define ADD2(d,a,b)   asm("add.rn.f32x2 %0, %1, %2;"     : "=l"(d) : "l"(a), "l"(b))
#define MUL2(d,a,b)   asm("mul.rn.f32x2 %0, %1, %2;"     : "=l"(d) : "l"(a), "l"(b))
#define PACK2(d,lo,hi) asm("mov.b64 %0, {%1, %2};" : "=l"(d) : "f"(lo), "f"(hi))
#define UNPACK2(lo,hi,s) asm("mov.b64 {%0, %1}, %2;" : "=f"(lo), "=f"(hi) : "l"(s))
__device__ __forceinline__ float ex2f(float a) {
    float r; asm("ex2.approx.f32 %0, %1;" : "=f"(r) : "f"(a)); return r;
}

__device__ __forceinline__ unsigned f2key(float f) {
    unsigned u = __float_as_uint(f);
    return (u & 0x80000000u) ? ~u : (u | 0x80000000u);
}
__device__ __forceinline__ float key2f(unsigned k) {
    unsigned u = (k & 0x80000000u) ? (k ^ 0x80000000u) : ~k;
    return __uint_as_float(u);
}

__global__ void k_init() {
    g_minbits = 0xFFFFFFFFu;
    g_maxbits = 0u;
}

__global__ void k_minmax(const float* __restrict__ y) {
    unsigned tid = blockIdx.x * blockDim.x + threadIdx.x;
    unsigned stride = gridDim.x * blockDim.x;
    unsigned mn = 0xFFFFFFFFu, mx = 0u;
    for (unsigned i = tid; i < (unsigned)NPIX; i += stride) {
        unsigned k = f2key(y[i]);
        mn = min(mn, k);
        mx = max(mx, k);
    }
    #pragma unroll
    for (int o = 16; o; o >>= 1) {
        mn = min(mn, __shfl_xor_sync(0xFFFFFFFFu, mn, o));
        mx = max(mx, __shfl_xor_sync(0xFFFFFFFFu, mx, o));
    }
    if ((threadIdx.x & 31u) == 0u) {
        atomicMin(&g_minbits, mn);
        atomicMax(&g_maxbits, mx);
    }
}

__global__ void k_final(const float* __restrict__ r) {
    float mx = key2f(g_maxbits), mn = key2f(g_minbits);
    float sigma = r[0] * (mx - mn);
    float h = sigma * 0.5f;
    g_C = -LOG2E / (h * h);
}

// ---- fused 9x9 box (zero padding, /81) + detail derivation ----
__global__ __launch_bounds__(256) void k_box(const float* __restrict__ X,
                                             const float* __restrict__ Y) {
    __shared__ float2 raw[16][40];  // rows by-4..by+11, cols bx-4..bx+35
    __shared__ float2 hs[16][32];

    int tx = threadIdx.x, ty = threadIdx.y;
    int bx = blockIdx.x * 32, by = blockIdx.y * 8;
    int tid = ty * 32 + tx;

    for (int k = tid; k < 16 * 40; k += 256) {
        int r = k / 40, c = k % 40;
        int gi = by + r - 4, gj = bx + c - 4;
        float2 v = make_float2(0.f, 0.f);
        if ((unsigned)gi < 512u && (unsigned)gj < 512u) {
            int idx = (gi << 9) + gj;
            v = make_float2(X[idx], Y[idx]);
        }
        raw[r][c] = v;
    }
    __syncthreads();

    for (int k = tid; k < 16 * 32; k += 256) {
        int r = k >> 5, c = k & 31;
        float sx = 0.f, sy = 0.f;
        #pragma unroll
        for (int d = 0; d < 9; ++d) {
            float2 v = raw[r][c + d];
            sx += v.x; sy += v.y;
        }
        hs[r][c] = make_float2(sx, sy);
    }
    __syncthreads();

    float sx = 0.f, sy = 0.f;
    #pragma unroll
    for (int d = 0; d < 9; ++d) {
        float2 v = hs[ty + d][tx];
        sx += v.x; sy += v.y;
    }
    const float inv81 = 1.0f / 81.0f;
    float xb = sx * inv81, yb = sy * inv81;
    float2 ctr = raw[ty + 4][tx + 4];
    float xd = ctr.x - xb;
    float zd = (ctr.y - yb) - xd;
    int idx = ((by + ty) << 9) + bx + tx;
    g_base[idx] = make_float2(xb, yb);
    g_det[idx]  = make_float2(xd, zd);
}

#define BX 32
#define BY 8
#define HB 9
#define TW (BX + 2 * HB + 1)   // 51 (extra pad col for the dj=19 packed lane)
#define TH (BY + 2 * HB)       // 26
#define HDR 2
#define HDC 4
#define DW (BX + 2 * HDC + 1)  // 41 (extra pad col for the dj=9 packed lane)
#define DH (BY + 2 * HDR)      // 12

__global__ __launch_bounds__(256) void k_main(float* __restrict__ out) {
    __shared__ float2 sb[TH][TW];
    __shared__ float2 sd[DH][DW];

    int tx = threadIdx.x, ty = threadIdx.y;
    int bx = blockIdx.x * BX, by = blockIdx.y * BY;
    int tid = ty * BX + tx;

    for (int k = tid; k < TH * TW; k += 256) {
        int r = k / TW, c = k % TW;
        int gi = min(max(by + r - HB, 0), 511);
        int gj = min(max(bx + c - HB, 0), 511);
        sb[r][c] = g_base[(gi << 9) + gj];
    }
    for (int k = tid; k < DH * DW; k += 256) {
        int r = k / DW, c = k % DW;
        int gi = min(max(by + r - HDR, 0), 511);
        int gj = min(max(bx + c - HDC, 0), 511);
        sd[r][c] = g_det[(gi << 9) + gj];
    }
    __syncthreads();

    int gi = by + ty, gj = bx + tx;

    // chunk window
    int kch = (gj - 1) / 62;
    kch = min(kch, 8);
    int cs = 62 * kch;
    int ce = min(cs + 64, 512);

    float Cs = g_C;                 // already * log2e
    u64 C2; PACK2(C2, Cs, Cs);

    const float invS1L = LOG2E / 8145.0625f;   // (19*19/4)^2
    const float invS0L = LOG2E / 126.5625f;    // (5*9/4)^2

    // ---------------- Base: 19x19 ----------------
    float2 cb = sb[ty + HB][tx + HB];
    float xc = cb.x;
    float nxc = -xc;
    u64 negxc2; PACK2(negxc2, nxc, nxc);

    // per-thread packed column table: spatial term (log2 domain), -1e30 if masked
    u64 Lb[10];
    {
        float Ls[20];
        #pragma unroll
        for (int dj = 0; dj < 20; ++dj) {
            float lv = -1e30f;
            if (dj < 19) {
                int jj = gj - HB + dj;
                if (jj >= cs && jj < ce) {
                    int cc = dj - HB;
                    lv = -(float)(cc * cc) * invS1L;
                }
            }
            Ls[dj] = lv;
        }
        #pragma unroll
        for (int p = 0; p < 10; ++p) PACK2(Lb[p], Ls[2 * p], Ls[2 * p + 1]);
    }

    u64 sw2 = 0ull, swx2 = 0ull, swxx2 = 0ull, swy2 = 0ull, swxy2 = 0ull;

    #pragma unroll 1
    for (int di = 0; di < 19; ++di) {
        int dd = di - HB;
        float elr = ex2f(-(float)(dd * dd) * invS1L);
        if ((unsigned)(gi + dd) >= 512u) elr = 0.f;
        u64 elr2; PACK2(elr2, elr, elr);

        u64 rw = 0ull, rwx = 0ull, rwxx = 0ull, rwy = 0ull, rwxy = 0ull;
        const float2* row = &sb[ty + di][tx];
        #pragma unroll
        for (int p = 0; p < 10; ++p) {
            float2 v0 = row[2 * p];
            float2 v1 = row[2 * p + 1];
            u64 vx2, vy2;
            PACK2(vx2, v0.x, v1.x);
            PACK2(vy2, v0.y, v1.y);
            u64 d2, t2, a2;
            ADD2(d2, vx2, negxc2);
            MUL2(t2, d2, C2);
            FMA2(a2, t2, d2, Lb[p]);
            float a0, a1; UNPACK2(a0, a1, a2);
            float w0 = ex2f(a0), w1 = ex2f(a1);
            u64 w2; PACK2(w2, w0, w1);
            ADD2(rw, rw, w2);
            u64 wx2; MUL2(wx2, w2, vx2);
            ADD2(rwx, rwx, wx2);
            FMA2(rwxx, wx2, vx2, rwxx);
            FMA2(rwy, w2, vy2, rwy);
            FMA2(rwxy, wx2, vy2, rwxy);
        }
        FMA2(sw2,   elr2, rw,   sw2);
        FMA2(swx2,  elr2, rwx,  swx2);
        FMA2(swxx2, elr2, rwxx, swxx2);
        FMA2(swy2,  elr2, rwy,  swy2);
        FMA2(swxy2, elr2, rwxy, swxy2);
    }

    float sw, swx, swxx, swy, swxy;
    { float a, b; UNPACK2(a, b, sw2);   sw   = a + b; }
    { float a, b; UNPACK2(a, b, swx2);  swx  = a + b; }
    { float a, b; UNPACK2(a, b, swxx2); swxx = a + b; }
    { float a, b; UNPACK2(a, b, swy2);  swy  = a + b; }
    { float a, b; UNPACK2(a, b, swxy2); swxy = a + b; }

    // ---------------- Detail: 5x9 ----------------
    float2 cd = sd[ty + HDR][tx + HDC];
    float nxd = -cd.x;
    u64 negxd2; PACK2(negxd2, nxd, nxd);

    u64 Ld[5];
    {
        float Ls[10];
        #pragma unroll
        for (int dj = 0; dj < 10; ++dj) {
            float lv = -1e30f;
            if (dj < 9) {
                int jj = gj - HDC + dj;
                if (jj >= cs && jj < ce) {
                    int cc = dj - HDC;
                    lv = -(float)(cc * cc) * invS0L;
                }
            }
            Ls[dj] = lv;
        }
        #pragma unroll
        for (int p = 0; p < 5; ++p) PACK2(Ld[p], Ls[2 * p], Ls[2 * p + 1]);
    }

    u64 swd2 = 0ull, swdz2 = 0ull;
    #pragma unroll
    for (int di = 0; di < 5; ++di) {
        int dd = di - HDR;
        float elr = ex2f(-(float)(dd * dd) * invS0L);
        if ((unsigned)(gi + dd) >= 512u) elr = 0.f;
        u64 elr2; PACK2(elr2, elr, elr);

        u64 rw = 0ull, rwz = 0ull;
        const float2* row = &sd[ty + di][tx];
        #pragma unroll
        for (int p = 0; p < 5; ++p) {
            float2 v0 = row[2 * p];
            float2 v1 = row[2 * p + 1];
            u64 vx2, vy2;
            PACK2(vx2, v0.x, v1.x);
            PACK2(vy2, v0.y, v1.y);
            u64 d2, t2, a2;
            ADD2(d2, vx2, negxd2);
            MUL2(t2, d2, C2);
            FMA2(a2, t2, d2, Ld[p]);
            float a0, a1; UNPACK2(a0, a1, a2);
            float w0 = ex2f(a0), w1 = ex2f(a1);
            u64 w2; PACK2(w2, w0, w1);
            ADD2(rw, rw, w2);
            FMA2(rwz, w2, vy2, rwz);
        }
        FMA2(swd2,  elr2, rw,  swd2);
        FMA2(swdz2, elr2, rwz, swdz2);
    }
    float swd, swdz;
    { float a, b; UNPACK2(a, b, swd2);  swd  = a + b; }
    { float a, b; UNPACK2(a, b, swdz2); swdz = a + b; }

    // ---------------- Combine ----------------
    float invsw = 1.0f / sw;
    float mx = swx * invsw, my = swy * invsw;
    float var = fmaf(-mx, mx, swxx * invsw);
    float cov = fmaf(-mx, my, swxy * invsw);
    float A = cov / (var + 1e-6f);
    float b = fmaf(-A, mx, my);
    float bdet = swdz / swd;

    out[(gi << 9) + gj] = fmaf(A, xc, b + cd.x + bdet);
}

extern "C" void kernel_launch(void* const* d_in, const int* in_sizes, int n_in,
                              void* d_out, int out_size) {
    const float* X = (const float*)d_in[0];
    const float* Y = (const float*)d_in[1];
    const float* R = (const float*)d_in[2];
    float* out = (float*)d_out;

    k_init<<<1, 1>>>();
    k_minmax<<<256, 256>>>(Y);
    k_final<<<1, 1>>>(R);
    k_box<<<dim3(16, 64), dim3(32, 8)>>>(X, Y);
    k_main<<<dim3(NN / BX, MM / BY), dim3(BX, BY)>>>(out);
}

// round 5
// speedup vs baseline: 1.2296x; 1.1314x over previous
#include <cuda_runtime.h>

#define MM 512
#define NN 512
#define NPIX (MM*NN)

typedef unsigned long long u64;

__device__ float2 g_base[NPIX];   // {Xb, yb}
__device__ float2 g_det[NPIX];    // {Xd, yd - Xd}
__device__ unsigned g_minbits, g_maxbits;
__device__ float g_C;             // -log2e/(sigma/2)^2

#define LOG2E 1.4426950408889634f

#define FMA2(d,a,b,c) asm("fma.rn.f32x2 %0, %1, %2, %3;" : "=l"(d) : "l"(a), "l"(b), "l"(c))
#define ADD2(d,a,b)   asm("add.rn.f32x2 %0, %1, %2;"     : "=l"(d) : "l"(a), "l"(b))
#define MUL2(d,a,b)   asm("mul.rn.f32x2 %0, %1, %2;"     : "=l"(d) : "l"(a), "l"(b))
#define PACK2(d,lo,hi) asm("mov.b64 %0, {%1, %2};" : "=l"(d) : "f"(lo), "f"(hi))
#define UNPACK2(lo,hi,s) asm("mov.b64 {%0, %1}, %2;" : "=f"(lo), "=f"(hi) : "l"(s))
__device__ __forceinline__ float ex2f(float a) {
    float r; asm("ex2.approx.f32 %0, %1;" : "=f"(r) : "f"(a)); return r;
}

__device__ __forceinline__ unsigned f2key(float f) {
    unsigned u = __float_as_uint(f);
    return (u & 0x80000000u) ? ~u : (u | 0x80000000u);
}
__device__ __forceinline__ float key2f(unsigned k) {
    unsigned u = (k & 0x80000000u) ? (k ^ 0x80000000u) : ~k;
    return __uint_as_float(u);
}

__global__ void k_init() { g_minbits = 0xFFFFFFFFu; g_maxbits = 0u; }

__global__ void k_minmax(const float* __restrict__ y) {
    unsigned tid = blockIdx.x * blockDim.x + threadIdx.x;
    unsigned stride = gridDim.x * blockDim.x;
    unsigned mn = 0xFFFFFFFFu, mx = 0u;
    for (unsigned i = tid; i < (unsigned)NPIX; i += stride) {
        unsigned k = f2key(y[i]);
        mn = min(mn, k); mx = max(mx, k);
    }
    #pragma unroll
    for (int o = 16; o; o >>= 1) {
        mn = min(mn, __shfl_xor_sync(0xFFFFFFFFu, mn, o));
        mx = max(mx, __shfl_xor_sync(0xFFFFFFFFu, mx, o));
    }
    if ((threadIdx.x & 31u) == 0u) {
        atomicMin(&g_minbits, mn);
        atomicMax(&g_maxbits, mx);
    }
}

__global__ void k_final(const float* __restrict__ r) {
    float mx = key2f(g_maxbits), mn = key2f(g_minbits);
    float sigma = r[0] * (mx - mn);
    float h = sigma * 0.5f;
    g_C = -LOG2E / (h * h);
}

// ---- fused 9x9 box (zero padding, /81) + detail derivation ----
__global__ __launch_bounds__(256) void k_box(const float* __restrict__ X,
                                             const float* __restrict__ Y) {
    __shared__ float2 raw[16][40];
    __shared__ float2 hs[16][32];

    int tx = threadIdx.x, ty = threadIdx.y;
    int bx = blockIdx.x * 32, by = blockIdx.y * 8;
    int tid = ty * 32 + tx;

    for (int k = tid; k < 16 * 40; k += 256) {
        int r = k / 40, c = k % 40;
        int gi = by + r - 4, gj = bx + c - 4;
        float2 v = make_float2(0.f, 0.f);
        if ((unsigned)gi < 512u && (unsigned)gj < 512u) {
            int idx = (gi << 9) + gj;
            v = make_float2(X[idx], Y[idx]);
        }
        raw[r][c] = v;
    }
    __syncthreads();

    for (int k = tid; k < 16 * 32; k += 256) {
        int r = k >> 5, c = k & 31;
        float sx = 0.f, sy = 0.f;
        #pragma unroll
        for (int d = 0; d < 9; ++d) {
            float2 v = raw[r][c + d];
            sx += v.x; sy += v.y;
        }
        hs[r][c] = make_float2(sx, sy);
    }
    __syncthreads();

    float sx = 0.f, sy = 0.f;
    #pragma unroll
    for (int d = 0; d < 9; ++d) {
        float2 v = hs[ty + d][tx];
        sx += v.x; sy += v.y;
    }
    const float inv81 = 1.0f / 81.0f;
    float xb = sx * inv81, yb = sy * inv81;
    float2 ctr = raw[ty + 4][tx + 4];
    float xd = ctr.x - xb;
    float zd = (ctr.y - yb) - xd;
    int idx = ((by + ty) << 9) + bx + tx;
    g_base[idx] = make_float2(xb, yb);
    g_det[idx]  = make_float2(xd, zd);
}

// ================= main bilateral kernel =================
// Tile: 32 cols x 8 rows. Block: 32x4 threads, 2 output rows per thread.
// Shared arrays hold OVERLAPPING PAIRS: s[r][c] = {v[c], v[c+1]}.
// Consumers read pairs at STRIDE 2: row[2p] = {v[tx+2p], v[tx+2p+1]}.
#define BX 32
#define TROW 26      // 8 + 2*9
#define TCOL 51      // 32 + 2*9 + 1
#define DROW 12      // 8 + 2*2
#define DCOL 41      // 32 + 2*4 + 1

__global__ __launch_bounds__(128) void k_main(float* __restrict__ out) {
    __shared__ float2 sbx[TROW][TCOL];
    __shared__ float2 sby[TROW][TCOL];
    __shared__ float2 sdx[DROW][DCOL];
    __shared__ float2 sdy[DROW][DCOL];

    int tx = threadIdx.x, ty = threadIdx.y;
    int bx = blockIdx.x * 32, by = blockIdx.y * 8;
    int tid = ty * 32 + tx;

    // Fill: value at (r,c) goes to [c].x and [c-1].y (overlapping pairs)
    for (int k = tid; k < TROW * TCOL; k += 128) {
        int r = k / TCOL, c = k % TCOL;
        int gi = min(max(by + r - 9, 0), 511);
        int gj = min(max(bx + c - 9, 0), 511);
        float2 v = g_base[(gi << 9) + gj];
        sbx[r][c].x = v.x;
        sby[r][c].x = v.y;
        if (c > 0) { sbx[r][c - 1].y = v.x; sby[r][c - 1].y = v.y; }
    }
    for (int k = tid; k < DROW * DCOL; k += 128) {
        int r = k / DCOL, c = k % DCOL;
        int gi = min(max(by + r - 2, 0), 511);
        int gj = min(max(bx + c - 4, 0), 511);
        float2 v = g_det[(gi << 9) + gj];
        sdx[r][c].x = v.x;
        sdy[r][c].x = v.y;
        if (c > 0) { sdx[r][c - 1].y = v.x; sdy[r][c - 1].y = v.y; }
    }
    __syncthreads();

    int ty2 = ty * 2;
    int gi0 = by + ty2;          // center 0 row; center 1 = gi0+1
    int gj  = bx + tx;

    // chunk window
    int kch = (gj - 1) / 62;
    kch = min(kch, 8);
    int cs = 62 * kch;
    int ce = min(cs + 64, 512);

    float Cs = g_C;
    u64 C2; PACK2(C2, Cs, Cs);

    const float invS1L = LOG2E / 8145.0625f;   // (19*19/4)^2
    const float invS0L = LOG2E / 126.5625f;    // (5*9/4)^2

    // ---------------- Base: 19x19, two centers ----------------
    float xc0 = sbx[ty2 + 9][tx + 9].x;
    float xc1 = sbx[ty2 + 10][tx + 9].x;
    u64 nx0, nx1;
    { float a = -xc0; PACK2(nx0, a, a); }
    { float a = -xc1; PACK2(nx1, a, a); }

    // packed col table: spatial (log2) or -1e30 masked; shared by both centers
    u64 Lb[10];
    {
        #pragma unroll
        for (int p = 0; p < 10; ++p) {
            float l0 = -1e30f, l1 = -1e30f;
            int dj0 = 2 * p, dj1 = 2 * p + 1;
            int j0 = gj - 9 + dj0, j1 = gj - 9 + dj1;
            if (j0 >= cs && j0 < ce) { int cc = dj0 - 9; l0 = -(float)(cc * cc) * invS1L; }
            if (dj1 < 19 && j1 >= cs && j1 < ce) { int cc = dj1 - 9; l1 = -(float)(cc * cc) * invS1L; }
            PACK2(Lb[p], l0, l1);
        }
    }

    u64 g0 = 0, g1 = 0, g2 = 0, g3 = 0, g4 = 0;      // center0: w, wx, wxx, wy, wxy
    u64 h0 = 0, h1 = 0, h2 = 0, h3 = 0, h4 = 0;      // center1

    #pragma unroll 1
    for (int r = 0; r < 20; ++r) {
        bool rowok = (unsigned)(gi0 + r - 9) < 512u;
        int d0 = r - 9, d1 = r - 10;
        float e0 = (r <= 18 && rowok) ? ex2f(-(float)(d0 * d0) * invS1L) : 0.f;
        float e1 = (r >= 1 && rowok) ? ex2f(-(float)(d1 * d1) * invS1L) : 0.f;

        const u64* rbx = (const u64*)&sbx[ty2 + r][tx];
        const u64* rby = (const u64*)&sby[ty2 + r][tx];

        u64 p0 = 0, p1 = 0, p2 = 0, p3 = 0, p4 = 0;
        u64 q0 = 0, q1 = 0, q2 = 0, q3 = 0, q4 = 0;
        #pragma unroll
        for (int p = 0; p < 10; ++p) {
            u64 vx2 = rbx[2 * p];
            u64 vy2 = rby[2 * p];
            // center 0
            {
                u64 dd, t, a;
                ADD2(dd, vx2, nx0);
                MUL2(t, dd, C2);
                FMA2(a, t, dd, Lb[p]);
                float a0, a1; UNPACK2(a0, a1, a);
                float w0 = ex2f(a0), w1 = ex2f(a1);
                u64 w; PACK2(w, w0, w1);
                ADD2(p0, p0, w);
                u64 wx; MUL2(wx, w, vx2);
                ADD2(p1, p1, wx);
                FMA2(p2, wx, vx2, p2);
                FMA2(p3, w, vy2, p3);
                FMA2(p4, wx, vy2, p4);
            }
            // center 1
            {
                u64 dd, t, a;
                ADD2(dd, vx2, nx1);
                MUL2(t, dd, C2);
                FMA2(a, t, dd, Lb[p]);
                float a0, a1; UNPACK2(a0, a1, a);
                float w0 = ex2f(a0), w1 = ex2f(a1);
                u64 w; PACK2(w, w0, w1);
                ADD2(q0, q0, w);
                u64 wx; MUL2(wx, w, vx2);
                ADD2(q1, q1, wx);
                FMA2(q2, wx, vx2, q2);
                FMA2(q3, w, vy2, q3);
                FMA2(q4, wx, vy2, q4);
            }
        }
        u64 e02; PACK2(e02, e0, e0);
        u64 e12; PACK2(e12, e1, e1);
        FMA2(g0, e02, p0, g0); FMA2(g1, e02, p1, g1); FMA2(g2, e02, p2, g2);
        FMA2(g3, e02, p3, g3); FMA2(g4, e02, p4, g4);
        FMA2(h0, e12, q0, h0); FMA2(h1, e12, q1, h1); FMA2(h2, e12, q2, h2);
        FMA2(h3, e12, q3, h3); FMA2(h4, e12, q4, h4);
    }

    float A0, B0, A1, B1;
    {
        float a, b, sw, swx, swxx, swy, swxy;
        UNPACK2(a, b, g0); sw = a + b;
        UNPACK2(a, b, g1); swx = a + b;
        UNPACK2(a, b, g2); swxx = a + b;
        UNPACK2(a, b, g3); swy = a + b;
        UNPACK2(a, b, g4); swxy = a + b;
        float invsw = 1.0f / sw;
        float mx = swx * invsw, my = swy * invsw;
        float var = fmaf(-mx, mx, swxx * invsw);
        float cov = fmaf(-mx, my, swxy * invsw);
        A0 = cov / (var + 1e-6f);
        B0 = fmaf(-A0, mx, my);
    }
    {
        float a, b, sw, swx, swxx, swy, swxy;
        UNPACK2(a, b, h0); sw = a + b;
        UNPACK2(a, b, h1); swx = a + b;
        UNPACK2(a, b, h2); swxx = a + b;
        UNPACK2(a, b, h3); swy = a + b;
        UNPACK2(a, b, h4); swxy = a + b;
        float invsw = 1.0f / sw;
        float mx = swx * invsw, my = swy * invsw;
        float var = fmaf(-mx, mx, swxx * invsw);
        float cov = fmaf(-mx, my, swxy * invsw);
        A1 = cov / (var + 1e-6f);
        B1 = fmaf(-A1, mx, my);
    }

    // ---------------- Detail: 5x9, two centers ----------------
    u64 Ld[5];
    {
        #pragma unroll
        for (int p = 0; p < 5; ++p) {
            float l0 = -1e30f, l1 = -1e30f;
            int dj0 = 2 * p, dj1 = 2 * p + 1;
            int j0 = gj - 4 + dj0, j1 = gj - 4 + dj1;
            if (j0 >= cs && j0 < ce) { int cc = dj0 - 4; l0 = -(float)(cc * cc) * invS0L; }
            if (dj1 < 9 && j1 >= cs && j1 < ce) { int cc = dj1 - 4; l1 = -(float)(cc * cc) * invS0L; }
            PACK2(Ld[p], l0, l1);
        }
    }

    float bd[2], xd[2];
    #pragma unroll
    for (int c = 0; c < 2; ++c) {
        float xdc = sdx[ty2 + 2 + c][tx + 4].x;
        xd[c] = xdc;
        u64 nxd; { float a = -xdc; PACK2(nxd, a, a); }
        u64 s0 = 0, s1 = 0;
        #pragma unroll
        for (int di = 0; di < 5; ++di) {
            int dd = di - 2;
            float elr = ((unsigned)(gi0 + c + dd) < 512u) ? ex2f(-(float)(dd * dd) * invS0L) : 0.f;
            const u64* rdx = (const u64*)&sdx[ty2 + c + di][tx];
            const u64* rdy = (const u64*)&sdy[ty2 + c + di][tx];
            u64 r0 = 0, r1 = 0;
            #pragma unroll
            for (int p = 0; p < 5; ++p) {
                u64 vx2 = rdx[2 * p];
                u64 vy2 = rdy[2 * p];
                u64 dv, t, a;
                ADD2(dv, vx2, nxd);
                MUL2(t, dv, C2);
                FMA2(a, t, dv, Ld[p]);
                float a0, a1; UNPACK2(a0, a1, a);
                float w0 = ex2f(a0), w1 = ex2f(a1);
                u64 w; PACK2(w, w0, w1);
                ADD2(r0, r0, w);
                FMA2(r1, w, vy2, r1);
            }
            u64 e2; PACK2(e2, elr, elr);
            FMA2(s0, e2, r0, s0);
            FMA2(s1, e2, r1, s1);
        }
        float a, b, swd, swdz;
        UNPACK2(a, b, s0); swd = a + b;
        UNPACK2(a, b, s1); swdz = a + b;
        bd[c] = swdz / swd;
    }

    out[(gi0 << 9) + gj]       = fmaf(A0, xc0, B0 + xd[0] + bd[0]);
    out[((gi0 + 1) << 9) + gj] = fmaf(A1, xc1, B1 + xd[1] + bd[1]);
}

extern "C" void kernel_launch(void* const* d_in, const int* in_sizes, int n_in,
                              void* d_out, int out_size) {
    const float* X = (const float*)d_in[0];
    const float* Y = (const float*)d_in[1];
    const float* R = (const float*)d_in[2];
    float* out = (float*)d_out;

    k_init<<<1, 1>>>();
    k_minmax<<<256, 256>>>(Y);
    k_final<<<1, 1>>>(R);
    k_box<<<dim3(16, 64), dim3(32, 8)>>>(X, Y);
    k_main<<<dim3(16, 64), dim3(32, 4)>>>(out);
}